// round 4
// baseline (speedup 1.0000x reference)
#include <cuda_runtime.h>
#include <cstdint>

#define BB 4
#define SEQ 2048
#define EMB 1024
#define NH 16
#define HD 64
#define MT (BB * SEQ)  // 8192 tokens

// Scratch (allocation-free rule: device globals)
__device__ float g_q[BB * NH * SEQ * HD];   // [b][h][s][d]
__device__ float g_k[BB * NH * SEQ * HD];
__device__ float g_v[BB * NH * SEQ * HD];
__device__ float g_ao[MT * EMB];            // attention out, [b][s][h*64+d] == [m][e]

// ---------------------------------------------------------------------------
// tf32 helpers (baseline PTX, works at .target sm_100)
// ---------------------------------------------------------------------------
__device__ __forceinline__ uint32_t f2tf32(float x) {
  uint32_t r;
  asm("cvt.rna.tf32.f32 %0, %1;" : "=r"(r) : "f"(x));
  return r;
}

__device__ __forceinline__ void split1(float v, uint32_t& h, uint32_t& l) {
  h = f2tf32(v);
  l = f2tf32(v - __uint_as_float(h));
}

__device__ __forceinline__ void mma_tf32(float* c, const uint32_t* a,
                                         const uint32_t* b) {
  asm volatile(
      "mma.sync.aligned.m16n8k8.row.col.f32.tf32.tf32.f32 "
      "{%0,%1,%2,%3}, {%4,%5,%6,%7}, {%8,%9}, {%0,%1,%2,%3};"
      : "+f"(c[0]), "+f"(c[1]), "+f"(c[2]), "+f"(c[3])
      : "r"(a[0]), "r"(a[1]), "r"(a[2]), "r"(a[3]), "r"(b[0]), "r"(b[1]));
}

// ---------------------------------------------------------------------------
// tf32 3x-split GEMM via mma.sync: D[m][n] = sum_k A[m][k]*B[n][k] + bias[n]
// CTA 128x128, BK=16, 256 threads (8 warps, each 64x32 out).
// MODE 0: A=query, scatter into g_q/g_k/g_v. MODE 1: A=g_ao, write out.
// ---------------------------------------------------------------------------
#define SPAD 20  // row stride in words for 16-col tile (conflict-free frags)

template <int MODE>
__global__ __launch_bounds__(256) void gemm_mma_kernel(
    const float* __restrict__ A, const float* __restrict__ B,
    const float* __restrict__ bias, float* __restrict__ out) {
  __shared__ uint32_t s_ahi[128 * SPAD];
  __shared__ uint32_t s_alo[128 * SPAD];
  __shared__ uint32_t s_bhi[128 * SPAD];
  __shared__ uint32_t s_blo[128 * SPAD];

  const int tid = threadIdx.x;
  const int lane = tid & 31;
  const int wid = tid >> 5;
  const int warp_m = wid & 1;        // 2 warps over M
  const int warp_n = wid >> 1;       // 4 warps over N
  const int m0 = blockIdx.y * 128;
  const int n0 = blockIdx.x * 128;

  const float* Asrc = (MODE == 0) ? A : g_ao;

  const int ldr = tid >> 2;          // rows 0..63 (+64 for second half)
  const int ldc = (tid & 3) * 4;     // 0,4,8,12

  const float* Ap0 = Asrc + (size_t)(m0 + ldr) * EMB + ldc;
  const float* Ap1 = Asrc + (size_t)(m0 + 64 + ldr) * EMB + ldc;
  const float* Bp0 = B + (size_t)(n0 + ldr) * EMB + ldc;
  const float* Bp1 = B + (size_t)(n0 + 64 + ldr) * EMB + ldc;

  float acc[4][4][4] = {};  // [mt][nt][reg]

  float4 pa0, pa1, pb0, pb1;
  pa0 = *(const float4*)(Ap0);
  pa1 = *(const float4*)(Ap1);
  pb0 = *(const float4*)(Bp0);
  pb1 = *(const float4*)(Bp1);

  const int s0 = ldr * SPAD + ldc;
  const int s1 = (ldr + 64) * SPAD + ldc;

  for (int c = 0; c < EMB / 16; ++c) {
    if (c > 0) __syncthreads();

    {
      uint4 h, l;
      split1(pa0.x, h.x, l.x); split1(pa0.y, h.y, l.y);
      split1(pa0.z, h.z, l.z); split1(pa0.w, h.w, l.w);
      *(uint4*)&s_ahi[s0] = h; *(uint4*)&s_alo[s0] = l;
      split1(pa1.x, h.x, l.x); split1(pa1.y, h.y, l.y);
      split1(pa1.z, h.z, l.z); split1(pa1.w, h.w, l.w);
      *(uint4*)&s_ahi[s1] = h; *(uint4*)&s_alo[s1] = l;
      split1(pb0.x, h.x, l.x); split1(pb0.y, h.y, l.y);
      split1(pb0.z, h.z, l.z); split1(pb0.w, h.w, l.w);
      *(uint4*)&s_bhi[s0] = h; *(uint4*)&s_blo[s0] = l;
      split1(pb1.x, h.x, l.x); split1(pb1.y, h.y, l.y);
      split1(pb1.z, h.z, l.z); split1(pb1.w, h.w, l.w);
      *(uint4*)&s_bhi[s1] = h; *(uint4*)&s_blo[s1] = l;
    }
    __syncthreads();

    if (c + 1 < EMB / 16) {
      const int off = (c + 1) * 16;
      pa0 = *(const float4*)(Ap0 + off);
      pa1 = *(const float4*)(Ap1 + off);
      pb0 = *(const float4*)(Bp0 + off);
      pb1 = *(const float4*)(Bp1 + off);
    }

#pragma unroll
    for (int kc = 0; kc < 2; ++kc) {
      const int kb = kc * 8 + (lane & 3);
      uint32_t ah[4][4], al[4][4];
#pragma unroll
      for (int mt = 0; mt < 4; ++mt) {
        const int r = warp_m * 64 + mt * 16 + (lane >> 2);
        const int i0 = r * SPAD + kb;
        const int i1 = (r + 8) * SPAD + kb;
        ah[mt][0] = s_ahi[i0];     ah[mt][1] = s_ahi[i1];
        ah[mt][2] = s_ahi[i0 + 4]; ah[mt][3] = s_ahi[i1 + 4];
        al[mt][0] = s_alo[i0];     al[mt][1] = s_alo[i1];
        al[mt][2] = s_alo[i0 + 4]; al[mt][3] = s_alo[i1 + 4];
      }
      uint32_t bh[4][2], bl[4][2];
#pragma unroll
      for (int nt = 0; nt < 4; ++nt) {
        const int n = warp_n * 32 + nt * 8 + (lane >> 2);
        const int i0 = n * SPAD + kb;
        bh[nt][0] = s_bhi[i0]; bh[nt][1] = s_bhi[i0 + 4];
        bl[nt][0] = s_blo[i0]; bl[nt][1] = s_blo[i0 + 4];
      }
#pragma unroll
      for (int mt = 0; mt < 4; ++mt)
#pragma unroll
        for (int nt = 0; nt < 4; ++nt) {
          mma_tf32(acc[mt][nt], ah[mt], bh[nt]);
          mma_tf32(acc[mt][nt], ah[mt], bl[nt]);
          mma_tf32(acc[mt][nt], al[mt], bh[nt]);
        }
    }
  }

#pragma unroll
  for (int mt = 0; mt < 4; ++mt) {
#pragma unroll
    for (int nt = 0; nt < 4; ++nt) {
      const int r = m0 + warp_m * 64 + mt * 16 + (lane >> 2);
      const int n = n0 + warp_n * 32 + nt * 8 + (lane & 3) * 2;
      const float b0 = bias[n], b1 = bias[n + 1];
      float2 v0 = {acc[mt][nt][0] + b0, acc[mt][nt][1] + b1};
      float2 v1 = {acc[mt][nt][2] + b0, acc[mt][nt][3] + b1};
      if (MODE == 0) {
        const int which = n >> 10;
        float* dstv = (which == 0) ? g_q : (which == 1) ? g_k : g_v;
        const int rem = n & 1023;
        const int h = rem >> 6;
        const int d = rem & 63;
        const int b_ = r >> 11, s_ = r & 2047;
        float* base = dstv + (size_t)(((b_ << 4) + h) * SEQ) * HD + d;
        *(float2*)(base + (size_t)s_ * HD) = v0;
        *(float2*)(base + (size_t)(s_ + 8) * HD) = v1;
      } else {
        *(float2*)(out + (size_t)r * EMB + n) = v0;
        *(float2*)(out + (size_t)(r + 8) * EMB + n) = v1;
      }
    }
  }
}

// ---------------------------------------------------------------------------
// Flash attention with mma.sync tf32 3x-split.
// CTA: 64 q-rows, 4 warps (warp w owns rows w*16..w*16+15). KV tiles of 32.
// K/V/P stored in smem as packed uint2 fragment pairs:
//   K2[key][ks*4+qp]  = (K[key][ks*8+qp],   K[key][ks*8+qp+4])
//   V2[d][kst*4+qp]   = (V[kst*8+qp][d],    V[kst*8+qp+4][d])
//   P2[row][kst*4+qp] = (P[row][kst*8+qp],  P[row][kst*8+qp+4])
// Row strides: K2=36 uint2 (72w), V2/P2=20 uint2 (40w) -> stride ≡ 8 (mod 32)
// words -> conflict-free LDS.64 fragment fetches.
// scores scaled by 1/sqrt(EMB) = 1/32.
// ---------------------------------------------------------------------------
struct AttnSmem {
  float Qs[64][68];        // staging for Q (17408 B)
  uint2 K2h[32][36];       // 9216 B
  uint2 K2l[32][36];
  uint2 V2h[64][20];       // 10240 B
  uint2 V2l[64][20];
  uint2 P2h[64][20];
  uint2 P2l[64][20];
};
#define ATTN_SMEM_BYTES sizeof(AttnSmem)

__global__ __launch_bounds__(128) void flash_mma_kernel() {
  extern __shared__ char dsm_raw[];
  AttnSmem* sm = reinterpret_cast<AttnSmem*>(dsm_raw);

  const int tid = threadIdx.x;
  const int lane = tid & 31;
  const int w = tid >> 5;
  const int grp = lane >> 2;     // 0..7
  const int qp = lane & 3;       // 0..3
  const int bh = blockIdx.x;     // 0..63
  const int q0 = blockIdx.y * 64;
  const int b = bh >> 4, h = bh & 15;
  const int qrow = w * 16 + grp;

  const float* Qg = g_q + (size_t)(bh * SEQ + q0) * HD;
  const float* Kg = g_k + (size_t)bh * SEQ * HD;
  const float* Vg = g_v + (size_t)bh * SEQ * HD;

  // ---- load Q tile (64x64) to smem, coalesced ----
#pragma unroll
  for (int it = 0; it < 8; ++it) {
    const int slot = it * 128 + tid;   // 0..1023 float4 slots
    const int r = slot >> 4;
    const int c = (slot & 15) * 4;
    *(float4*)&sm->Qs[r][c] = *(const float4*)(Qg + r * HD + c);
  }
  __syncthreads();

  // ---- extract per-thread Q fragments (held in regs for whole CTA) ----
  uint32_t qh[8][4], ql[8][4];
#pragma unroll
  for (int ks = 0; ks < 8; ++ks) {
    split1(sm->Qs[qrow][ks * 8 + qp],          qh[ks][0], ql[ks][0]);
    split1(sm->Qs[qrow + 8][ks * 8 + qp],      qh[ks][1], ql[ks][1]);
    split1(sm->Qs[qrow][ks * 8 + qp + 4],      qh[ks][2], ql[ks][2]);
    split1(sm->Qs[qrow + 8][ks * 8 + qp + 4],  qh[ks][3], ql[ks][3]);
  }

  float o[8][4] = {};                  // O accum [d-tile][reg]
  float m0v = -1e30f, m1v = -1e30f;    // row maxima (scaled domain)
  float l0v = 0.f, l1v = 0.f;
  const float SCALE = 0.03125f;        // 1/sqrt(1024)

  for (int j0 = 0; j0 < SEQ; j0 += 32) {
    __syncthreads();   // smem K/V consumed by previous iteration

    // ---- load + split K,V tile (32 keys x 64 d) into packed layouts ----
#pragma unroll
    for (int it = 0; it < 4; ++it) {
      const int slot = it * 128 + tid;  // 0..511 float4 slots
      const int key = slot >> 4;        // 0..31
      const int c4 = (slot & 15) * 4;   // 0..60
      const float4 kv = *(const float4*)(Kg + (size_t)(j0 + key) * HD + c4);
      const float4 vv = *(const float4*)(Vg + (size_t)(j0 + key) * HD + c4);
      const float ka[4] = {kv.x, kv.y, kv.z, kv.w};
      const float va[4] = {vv.x, vv.y, vv.z, vv.w};
      const int kst = key >> 3;
      const int kidx = kst * 4 + (key & 3);
      const int kcomp = (key >> 2) & 1;
#pragma unroll
      for (int j = 0; j < 4; ++j) {
        const int d = c4 + j;
        uint32_t hv, lv;
        // K element (key, d)
        split1(ka[j], hv, lv);
        const int ks = d >> 3;
        const int idx = ks * 4 + (d & 3);
        const int comp = (d >> 2) & 1;
        ((uint32_t*)&sm->K2h[key][idx])[comp] = hv;
        ((uint32_t*)&sm->K2l[key][idx])[comp] = lv;
        // V element (key, d) -> V2[d][kidx]
        split1(va[j], hv, lv);
        ((uint32_t*)&sm->V2h[d][kidx])[kcomp] = hv;
        ((uint32_t*)&sm->V2l[d][kidx])[kcomp] = lv;
      }
    }
    __syncthreads();

    // ---- S = Q @ K^T (raw), 4 n-tiles of 8 keys ----
    float s[4][4] = {};
#pragma unroll
    for (int nt = 0; nt < 4; ++nt) {
#pragma unroll
      for (int ks = 0; ks < 8; ++ks) {
        const uint2 bhv = sm->K2h[nt * 8 + grp][ks * 4 + qp];
        const uint2 blv = sm->K2l[nt * 8 + grp][ks * 4 + qp];
        uint32_t bh2[2] = {bhv.x, bhv.y};
        uint32_t bl2[2] = {blv.x, blv.y};
        mma_tf32(s[nt], qh[ks], bh2);
        mma_tf32(s[nt], qh[ks], bl2);
        mma_tf32(s[nt], ql[ks], bh2);
      }
    }

    // ---- online softmax (rows qrow, qrow+8 per lane-group) ----
    float mx0 = -1e30f, mx1 = -1e30f;
#pragma unroll
    for (int nt = 0; nt < 4; ++nt) {
      mx0 = fmaxf(mx0, fmaxf(s[nt][0], s[nt][1]));
      mx1 = fmaxf(mx1, fmaxf(s[nt][2], s[nt][3]));
    }
    mx0 = fmaxf(mx0, __shfl_xor_sync(0xffffffffu, mx0, 1));
    mx0 = fmaxf(mx0, __shfl_xor_sync(0xffffffffu, mx0, 2));
    mx1 = fmaxf(mx1, __shfl_xor_sync(0xffffffffu, mx1, 1));
    mx1 = fmaxf(mx1, __shfl_xor_sync(0xffffffffu, mx1, 2));
    const float mn0 = fmaxf(m0v, mx0 * SCALE);
    const float mn1 = fmaxf(m1v, mx1 * SCALE);
    const float c0 = __expf(m0v - mn0);
    const float c1 = __expf(m1v - mn1);
    m0v = mn0; m1v = mn1;

    float ls0 = 0.f, ls1 = 0.f;
    float p[4][4];
#pragma unroll
    for (int nt = 0; nt < 4; ++nt) {
      p[nt][0] = __expf(s[nt][0] * SCALE - mn0);
      p[nt][1] = __expf(s[nt][1] * SCALE - mn0);
      p[nt][2] = __expf(s[nt][2] * SCALE - mn1);
      p[nt][3] = __expf(s[nt][3] * SCALE - mn1);
      ls0 += p[nt][0] + p[nt][1];
      ls1 += p[nt][2] + p[nt][3];
    }
    ls0 += __shfl_xor_sync(0xffffffffu, ls0, 1);
    ls0 += __shfl_xor_sync(0xffffffffu, ls0, 2);
    ls1 += __shfl_xor_sync(0xffffffffu, ls1, 1);
    ls1 += __shfl_xor_sync(0xffffffffu, ls1, 2);
    l0v = l0v * c0 + ls0;
    l1v = l1v * c1 + ls1;

    // rescale O
#pragma unroll
    for (int nt2 = 0; nt2 < 8; ++nt2) {
      o[nt2][0] *= c0; o[nt2][1] *= c0;
      o[nt2][2] *= c1; o[nt2][3] *= c1;
    }

    // ---- stage P (split) into warp-private smem rows ----
#pragma unroll
    for (int nt = 0; nt < 4; ++nt) {
#pragma unroll
      for (int j = 0; j < 2; ++j) {
        const int col = nt * 8 + qp * 2 + j;
        const int kst = col >> 3;
        const int idx = kst * 4 + (col & 3);
        const int comp = (col >> 2) & 1;
        uint32_t hv, lv;
        split1(p[nt][j], hv, lv);       // row qrow
        ((uint32_t*)&sm->P2h[qrow][idx])[comp] = hv;
        ((uint32_t*)&sm->P2l[qrow][idx])[comp] = lv;
        split1(p[nt][2 + j], hv, lv);   // row qrow+8
        ((uint32_t*)&sm->P2h[qrow + 8][idx])[comp] = hv;
        ((uint32_t*)&sm->P2l[qrow + 8][idx])[comp] = lv;
      }
    }
    __syncwarp();

    // ---- O += P @ V ----
#pragma unroll
    for (int kst = 0; kst < 4; ++kst) {
      const uint2 pa0h = sm->P2h[qrow][kst * 4 + qp];
      const uint2 pa1h = sm->P2h[qrow + 8][kst * 4 + qp];
      const uint2 pa0l = sm->P2l[qrow][kst * 4 + qp];
      const uint2 pa1l = sm->P2l[qrow + 8][kst * 4 + qp];
      uint32_t ah2[4] = {pa0h.x, pa1h.x, pa0h.y, pa1h.y};
      uint32_t al2[4] = {pa0l.x, pa1l.x, pa0l.y, pa1l.y};
#pragma unroll
      for (int nt2 = 0; nt2 < 8; ++nt2) {
        const uint2 vbh = sm->V2h[nt2 * 8 + grp][kst * 4 + qp];
        const uint2 vbl = sm->V2l[nt2 * 8 + grp][kst * 4 + qp];
        uint32_t bh2[2] = {vbh.x, vbh.y};
        uint32_t bl2[2] = {vbl.x, vbl.y};
        mma_tf32(o[nt2], ah2, bh2);
        mma_tf32(o[nt2], ah2, bl2);
        mma_tf32(o[nt2], al2, bh2);
      }
    }
  }

  // ---- epilogue: divide by l, store to g_ao [b][s][h*64+d] ----
  const float il0 = 1.f / l0v;
  const float il1 = 1.f / l1v;
  float* aob = g_ao + ((size_t)(b * SEQ + q0) ) * EMB + h * HD;
#pragma unroll
  for (int nt2 = 0; nt2 < 8; ++nt2) {
    const int d0 = nt2 * 8 + qp * 2;
    float2 v0 = {o[nt2][0] * il0, o[nt2][1] * il0};
    float2 v1 = {o[nt2][2] * il1, o[nt2][3] * il1};
    *(float2*)(aob + (size_t)qrow * EMB + d0) = v0;
    *(float2*)(aob + (size_t)(qrow + 8) * EMB + d0) = v1;
  }
}

// ---------------------------------------------------------------------------
extern "C" void kernel_launch(void* const* d_in, const int* in_sizes, int n_in,
                              void* d_out, int out_size) {
  (void)in_sizes; (void)n_in; (void)out_size;
  const float* query = (const float*)d_in[0];
  // d_in[1]=key, d_in[2]=value: ignored by the reference module
  const float* Wqkv = (const float*)d_in[3];
  const float* bqkv = (const float*)d_in[4];
  const float* Wout = (const float*)d_in[5];
  const float* bout = (const float*)d_in[6];
  float* out = (float*)d_out;

  cudaFuncSetAttribute(flash_mma_kernel,
                       cudaFuncAttributeMaxDynamicSharedMemorySize,
                       (int)ATTN_SMEM_BYTES);

  dim3 g1(24, 64);   // 3072/128 x 8192/128
  gemm_mma_kernel<0><<<g1, 256>>>(query, Wqkv, bqkv, nullptr);

  dim3 g2(64, 32);   // (b*h) x (S/64)
  flash_mma_kernel<<<g2, 128, ATTN_SMEM_BYTES>>>();

  dim3 g3(8, 64);    // 1024/128 x 8192/128
  gemm_mma_kernel<1><<<g3, 256>>>(nullptr, Wout, bout, out);
}